// round 4
// baseline (speedup 1.0000x reference)
#include <cuda_runtime.h>
#include <math.h>

#define NN 256
#define BATCH 4096
#define N_MZIS 32640   // 256*255/2

// Scratch (no device allocations allowed)
__device__ float4 g_coef[N_MZIS];        // (cos th, sin th*cos ph, sin th*sin ph, 0)
__device__ float  g_Wt[NN * NN];         // g_Wt[j*NN + i] = Re(e^{i phe_i} U[i][j])

// ---------------------------------------------------------------------------
// Kernel A: per-MZI coefficients
// ---------------------------------------------------------------------------
__global__ void coef_kernel(const float* __restrict__ theta,
                            const float* __restrict__ phi) {
    int i = blockIdx.x * blockDim.x + threadIdx.x;
    if (i < N_MZIS) {
        float s, c;
        sincosf(theta[i], &s, &c);
        float ei, er;
        sincosf(phi[i], &ei, &er);
        g_coef[i] = make_float4(c, s * er, s * ei, 0.0f);
    }
}

// ---------------------------------------------------------------------------
// Kernel B: barrier-free systolic stream pipeline.
// Layer l is a stream transducer: consumes S_{l-1} = (v[0..255-(l-1)]) in
// order (v0 first, then v1 per step), emits n0 stream S_l, retires final n1
// as output row 255-l. Lane i of chain c owns layer 32c+i; intra-warp
// transport = shfl_up(1); chain boundaries (7) = smem FIFO + volatile
// counter (chunked release, consumer-only spin). Warp w runs chain w then
// chain w+4. Two columns per CTA packed in float4 {re0,im0,re1,im1}.
// Coefs: contiguous per layer -> 8-deep register ring via unroll-by-8.
// ---------------------------------------------------------------------------
__global__ __launch_bounds__(128, 1) void build_u_kernel(const float* __restrict__ phi_ext) {
    __shared__ float4 fifo[7][256];
    __shared__ int    fcnt[7];

    const int tid  = threadIdx.x;
    const int w    = tid >> 5;
    const int lane = tid & 31;
    const int j0   = blockIdx.x * 2;
    const int j1   = j0 + 1;

    if (tid < 7) fcnt[tid] = 0;
    __syncthreads();

    #pragma unroll 1
    for (int ph = 0; ph < 2; ++ph) {
        const int  c     = ph * 4 + w;                 // chain id 0..7
        const int  layer = 32 * c + lane;              // 255 = invalid (c=7,lane=31)
        const bool valid = (layer <= 254);
        const int  pmax  = 254 - layer;                // <0 if invalid
        const int  s0    = 2 * lane;                   // first active warp-step
        int basei = layer * 255 - ((layer * (layer - 1)) >> 1);
        if (basei > N_MZIS - 1) basei = N_MZIS - 1;    // clamp for invalid lane

        int S = (c < 7) ? (285 - 32 * c) : 61;         // last active step + 1
        S = (S + 7) & ~7;

        // coefficient ring prefill: slot u holds coef for first step s≡u (mod 8)
        float4 ring[8];
        #pragma unroll
        for (int u = 0; u < 8; ++u) {
            int p0  = (u - s0) & 7;
            int idx = basei + p0;
            if (idx > N_MZIS - 1) idx = N_MZIS - 1;
            ring[u] = __ldg(&g_coef[idx]);
        }

        float4 v0   = make_float4(0.f, 0.f, 0.f, 0.f);
        float4 outv = make_float4(0.f, 0.f, 0.f, 0.f);
        int avail = 0;

        // lane 0: initial v0 (stream head)
        if (lane == 0) {
            if (c == 0) {
                v0 = make_float4(j0 == 0 ? 1.f : 0.f, 0.f,
                                 j1 == 0 ? 1.f : 0.f, 0.f);
            } else {
                volatile int* vc = (volatile int*)&fcnt[c - 1];
                while ((avail = *vc) < 1) {}
                __threadfence_block();
                v0 = fifo[c - 1][0];
            }
        }

        #pragma unroll 1
        for (int sb = 0; sb < S; sb += 8) {
            #pragma unroll
            for (int u = 0; u < 8; ++u) {
                const int s = sb + u;
                // transport: previous step's n0 from lane-1
                float4 in;
                in.x = __shfl_up_sync(0xffffffffu, outv.x, 1);
                in.y = __shfl_up_sync(0xffffffffu, outv.y, 1);
                in.z = __shfl_up_sync(0xffffffffu, outv.z, 1);
                in.w = __shfl_up_sync(0xffffffffu, outv.w, 1);

                const int p = s - s0;
                if (lane > 0 && p == -1) v0 = in;      // grab stream head as v0

                if (valid && p >= 0 && p <= pmax) {
                    float4 v1;
                    if (lane == 0) {
                        if (c == 0) {
                            const int r = s + 1;
                            v1 = make_float4(r == j0 ? 1.f : 0.f, 0.f,
                                             r == j1 ? 1.f : 0.f, 0.f);
                        } else {
                            const int idx = s + 1;
                            if (idx >= avail) {
                                volatile int* vc = (volatile int*)&fcnt[c - 1];
                                while ((avail = *vc) <= idx) {}
                                __threadfence_block();
                            }
                            v1 = fifo[c - 1][idx];
                        }
                    } else {
                        v1 = in;
                    }

                    const float cc = ring[u].x, sr = ring[u].y, si = ring[u].z;
                    float4 n0, n1;
                    n0.x = cc * v0.x - sr * v1.x - si * v1.y;
                    n0.y = cc * v0.y - sr * v1.y + si * v1.x;
                    n0.z = cc * v0.z - sr * v1.z - si * v1.w;
                    n0.w = cc * v0.w - sr * v1.w + si * v1.z;
                    n1.x = sr * v0.x - si * v0.y + cc * v1.x;
                    n1.y = sr * v0.y + si * v0.x + cc * v1.y;
                    n1.z = sr * v0.z - si * v0.w + cc * v1.z;
                    n1.w = sr * v0.w + si * v0.z + cc * v1.w;
                    outv = n0;
                    v0   = n1;

                    // chain-boundary producer
                    if (lane == 31 && c < 7) {
                        fifo[c][p] = n0;
                        if ((p & 7) == 7 || p == pmax) {
                            __threadfence_block();
                            *((volatile int*)&fcnt[c]) = p + 1;
                        }
                    }

                    // retire final n1 -> row (255 - layer), with phase screen
                    if (p == pmax) {
                        const int r = 255 - layer;
                        float sp, cp;
                        sincosf(__ldg(&phi_ext[r]), &sp, &cp);
                        g_Wt[j0 * NN + r] = cp * n1.x - sp * n1.y;
                        g_Wt[j1 * NN + r] = cp * n1.z - sp * n1.w;
                        if (layer == 254) {            // its n0 is final row 0
                            float sp0, cp0;
                            sincosf(__ldg(&phi_ext[0]), &sp0, &cp0);
                            g_Wt[j0 * NN + 0] = cp0 * n0.x - sp0 * n0.y;
                            g_Wt[j1 * NN + 0] = cp0 * n0.z - sp0 * n0.w;
                        }
                    }
                }

                // ring reload for step s+8 (contiguous, 8-step lead)
                const int pn = s + 8 - s0;
                if (valid && pn >= 0 && pn <= pmax)
                    ring[u] = __ldg(&g_coef[basei + pn]);
            }
        }
    }
}

// ---------------------------------------------------------------------------
// Kernel C: out[b,i] = sum_j x[b,j] * Wt[j,i]
// BM=BN=64, BK=16, 256 threads, 4x4 per thread, float4 smem paths (pad +4).
// ---------------------------------------------------------------------------
#define BM 64
#define BN 64
#define BK 16

__global__ __launch_bounds__(256, 4) void gemm_kernel(const float* __restrict__ A,
                                                      float* __restrict__ C) {
    __shared__ float As[BK][BM + 4];
    __shared__ float Ws[BK][BN + 4];

    const int tid = threadIdx.x;
    const int tx = tid & 15;
    const int ty = tid >> 4;
    const int bm0 = blockIdx.x * BM;
    const int bn0 = blockIdx.y * BN;

    const int lr = tid >> 2;
    const int lc = (tid & 3) * 4;
    const int wr = tid >> 4;
    const int wc = (tid & 15) * 4;

    float acc[4][4] = {};

    for (int k0 = 0; k0 < NN; k0 += BK) {
        const float4 a4 = *reinterpret_cast<const float4*>(A + (bm0 + lr) * NN + k0 + lc);
        As[lc + 0][lr] = a4.x; As[lc + 1][lr] = a4.y;
        As[lc + 2][lr] = a4.z; As[lc + 3][lr] = a4.w;
        const float4 w4 = *reinterpret_cast<const float4*>(g_Wt + (k0 + wr) * NN + bn0 + wc);
        *reinterpret_cast<float4*>(&Ws[wr][wc]) = w4;
        __syncthreads();

        #pragma unroll
        for (int k = 0; k < BK; ++k) {
            const float4 am = *reinterpret_cast<const float4*>(&As[k][ty * 4]);
            const float4 bn = *reinterpret_cast<const float4*>(&Ws[k][tx * 4]);
            const float a[4] = {am.x, am.y, am.z, am.w};
            const float b[4] = {bn.x, bn.y, bn.z, bn.w};
            #pragma unroll
            for (int i = 0; i < 4; ++i)
                #pragma unroll
                for (int jj = 0; jj < 4; ++jj)
                    acc[i][jj] = fmaf(a[i], b[jj], acc[i][jj]);
        }
        __syncthreads();
    }

    #pragma unroll
    for (int i = 0; i < 4; ++i) {
        float4 r = make_float4(acc[i][0], acc[i][1], acc[i][2], acc[i][3]);
        *reinterpret_cast<float4*>(C + (bm0 + ty * 4 + i) * NN + bn0 + tx * 4) = r;
    }
}

// ---------------------------------------------------------------------------
// Launch: inputs (metadata order): x, theta, phi_internal, phi_external
// ---------------------------------------------------------------------------
extern "C" void kernel_launch(void* const* d_in, const int* in_sizes, int n_in,
                              void* d_out, int out_size) {
    const float* x       = (const float*)d_in[0];
    const float* theta   = (const float*)d_in[1];
    const float* phi_int = (const float*)d_in[2];
    const float* phi_ext = (const float*)d_in[3];
    float* out = (float*)d_out;

    coef_kernel<<<(N_MZIS + 255) / 256, 256>>>(theta, phi_int);
    build_u_kernel<<<NN / 2, 128>>>(phi_ext);
    gemm_kernel<<<dim3(BATCH / BM, NN / BN), 256>>>(x, out);
}

// round 6
// speedup vs baseline: 4.9477x; 4.9477x over previous
#include <cuda_runtime.h>
#include <math.h>

#define NN 256
#define BATCH 4096
#define TROWS 520          // padded step rows (active t: 0..508)

// Scratch (no device allocations allowed)
__device__ float4 g_coef2[TROWS * 128];  // [t][m]: coef for MZI at p=2m+(t&1); identity if inactive
__device__ float  g_Wt[NN * NN];         // g_Wt[j*NN + i] = Re(e^{i phe_i} U[i][j])

// ---------------------------------------------------------------------------
// Kernel A: schedule-ordered coefficients. (t,m) <-> (layer l, pos p) bijection
// on active entries; inactive slots get identity (1,0,0) so the build kernel
// needs no predication at all.
// ---------------------------------------------------------------------------
__global__ void coef2_kernel(const float* __restrict__ theta,
                             const float* __restrict__ phi) {
    const int t = blockIdx.x;        // 0..TROWS-1
    const int m = threadIdx.x;       // 0..127
    const int p = 2 * m + (t & 1);
    const int pmaxs = min(t, 508 - t);   // negative for t > 508
    float4 out = make_float4(1.f, 0.f, 0.f, 0.f);
    if (p <= pmaxs) {                // implies t <= 508, p <= 254, l in range
        const int l = (t - p) >> 1;
        const int idx = l * 255 - ((l * (l - 1)) >> 1) + p;
        float s, c;  sincosf(theta[idx], &s, &c);
        float ei, er; sincosf(phi[idx], &ei, &er);
        out = make_float4(c, s * er, s * ei, 0.f);
    }
    g_coef2[t * 128 + m] = out;
}

// ---------------------------------------------------------------------------
// Kernel B: one warp per column; rows 8i..8i+7 in lane i's registers.
// Even step: 4 internal MZIs (rows 0-1,2-3,4-5,6-7). Odd step: 3 internal
// (1-2,3-4,5-6) + boundary (7 | next lane's 0) via shfl. Identity coefs make
// the loop branch-free. 3-pair coef prefetch pipeline (~4-step lead).
// ---------------------------------------------------------------------------
#define MZI(cf, x0, y0, x1, y1) do {                       \
    const float c_ = (cf).x, sr_ = (cf).y, si_ = (cf).z;   \
    const float nx0 = c_*(x0) - sr_*(x1) - si_*(y1);       \
    const float ny0 = c_*(y0) - sr_*(y1) + si_*(x1);       \
    const float nx1 = sr_*(x0) - si_*(y0) + c_*(x1);       \
    const float ny1 = sr_*(y0) + si_*(x0) + c_*(y1);       \
    (x0) = nx0; (y0) = ny0; (x1) = nx1; (y1) = ny1;        \
} while (0)

#define LOADP(dst, tt) do {                                            \
    const float4* p_ = &g_coef2[(tt) * 128 + 4 * lane];                \
    dst[0] = __ldg(p_ + 0); dst[1] = __ldg(p_ + 1);                    \
    dst[2] = __ldg(p_ + 2); dst[3] = __ldg(p_ + 3);                    \
} while (0)

#define STEP_EVEN(cf) do {                                             \
    MZI(cf[0], vr[0], vi[0], vr[1], vi[1]);                            \
    MZI(cf[1], vr[2], vi[2], vr[3], vi[3]);                            \
    MZI(cf[2], vr[4], vi[4], vr[5], vi[5]);                            \
    MZI(cf[3], vr[6], vi[6], vr[7], vi[7]);                            \
} while (0)

#define STEP_ODD(cf) do {                                              \
    /* shfls first: vr/vi[0] and [7] untouched by interior MZIs */     \
    const float rx = __shfl_down_sync(0xffffffffu, vr[0], 1);          \
    const float ry = __shfl_down_sync(0xffffffffu, vi[0], 1);          \
    const float lx = __shfl_up_sync(0xffffffffu, vr[7], 1);            \
    const float ly = __shfl_up_sync(0xffffffffu, vi[7], 1);            \
    float bc = __shfl_up_sync(0xffffffffu, cf[3].x, 1);                \
    float bs = __shfl_up_sync(0xffffffffu, cf[3].y, 1);                \
    float bt = __shfl_up_sync(0xffffffffu, cf[3].z, 1);                \
    if (lane == 0) { bc = 1.f; bs = 0.f; bt = 0.f; }                   \
    MZI(cf[0], vr[1], vi[1], vr[2], vi[2]);                            \
    MZI(cf[1], vr[3], vi[3], vr[4], vi[4]);                            \
    MZI(cf[2], vr[5], vi[5], vr[6], vi[6]);                            \
    {   /* upper boundary: this lane's row 7 is v0 -> n0 */            \
        const float c_ = cf[3].x, sr_ = cf[3].y, si_ = cf[3].z;        \
        const float nx = c_*vr[7] - sr_*rx - si_*ry;                   \
        const float ny = c_*vi[7] - sr_*ry + si_*rx;                   \
        vr[7] = nx; vi[7] = ny;                                        \
    }                                                                  \
    {   /* lower boundary: this lane's row 0 is v1 -> n1 */            \
        const float nx = bs*lx - bt*ly + bc*vr[0];                     \
        const float ny = bs*ly + bt*lx + bc*vi[0];                     \
        vr[0] = nx; vi[0] = ny;                                        \
    }                                                                  \
} while (0)

__global__ __launch_bounds__(128, 1) void build_u_kernel(const float* __restrict__ phi_ext) {
    const int lane = threadIdx.x & 31;
    const int j = blockIdx.x * 4 + (threadIdx.x >> 5);   // column, one per warp

    float vr[8], vi[8];
    #pragma unroll
    for (int k = 0; k < 8; ++k) {
        vr[k] = (8 * lane + k == j) ? 1.f : 0.f;
        vi[k] = 0.f;
    }

    float4 e0[4], o0[4], e1[4], o1[4], e2[4], o2[4];
    LOADP(e0, 0); LOADP(o0, 1);
    LOADP(e1, 2); LOADP(o1, 3);
    LOADP(e2, 4); LOADP(o2, 5);

    int t = 6;
    #pragma unroll 1
    for (int it = 0; it < 85; ++it) {     // 85*6 = 510 steps (0..509; 509 inert)
        STEP_EVEN(e0); STEP_ODD(o0); LOADP(e0, t);     LOADP(o0, t + 1);
        STEP_EVEN(e1); STEP_ODD(o1); LOADP(e1, t + 2); LOADP(o1, t + 3);
        STEP_EVEN(e2); STEP_ODD(o2); LOADP(e2, t + 4); LOADP(o2, t + 5);
        t += 6;
    }

    // phase screen, real part, store column j (transposed W)
    #pragma unroll
    for (int k = 0; k < 8; ++k) {
        const int r = 8 * lane + k;
        float sp, cp;
        sincosf(__ldg(&phi_ext[r]), &sp, &cp);
        g_Wt[j * NN + r] = cp * vr[k] - sp * vi[k];
    }
}

// ---------------------------------------------------------------------------
// Kernel C: out[b,i] = sum_j x[b,j] * Wt[j,i]
// BM=BN=64, BK=16, 256 threads, 4x4 per thread, float4 smem paths (pad +4).
// ---------------------------------------------------------------------------
#define BM 64
#define BN 64
#define BK 16

__global__ __launch_bounds__(256, 4) void gemm_kernel(const float* __restrict__ A,
                                                      float* __restrict__ C) {
    __shared__ float As[BK][BM + 4];
    __shared__ float Ws[BK][BN + 4];

    const int tid = threadIdx.x;
    const int tx = tid & 15;
    const int ty = tid >> 4;
    const int bm0 = blockIdx.x * BM;
    const int bn0 = blockIdx.y * BN;

    const int lr = tid >> 2;
    const int lc = (tid & 3) * 4;
    const int wr = tid >> 4;
    const int wc = (tid & 15) * 4;

    float acc[4][4] = {};

    for (int k0 = 0; k0 < NN; k0 += BK) {
        const float4 a4 = *reinterpret_cast<const float4*>(A + (bm0 + lr) * NN + k0 + lc);
        As[lc + 0][lr] = a4.x; As[lc + 1][lr] = a4.y;
        As[lc + 2][lr] = a4.z; As[lc + 3][lr] = a4.w;
        const float4 w4 = *reinterpret_cast<const float4*>(g_Wt + (k0 + wr) * NN + bn0 + wc);
        *reinterpret_cast<float4*>(&Ws[wr][wc]) = w4;
        __syncthreads();

        #pragma unroll
        for (int k = 0; k < BK; ++k) {
            const float4 am = *reinterpret_cast<const float4*>(&As[k][ty * 4]);
            const float4 bn = *reinterpret_cast<const float4*>(&Ws[k][tx * 4]);
            const float a[4] = {am.x, am.y, am.z, am.w};
            const float b[4] = {bn.x, bn.y, bn.z, bn.w};
            #pragma unroll
            for (int i = 0; i < 4; ++i)
                #pragma unroll
                for (int jj = 0; jj < 4; ++jj)
                    acc[i][jj] = fmaf(a[i], b[jj], acc[i][jj]);
        }
        __syncthreads();
    }

    #pragma unroll
    for (int i = 0; i < 4; ++i) {
        float4 r = make_float4(acc[i][0], acc[i][1], acc[i][2], acc[i][3]);
        *reinterpret_cast<float4*>(C + (bm0 + ty * 4 + i) * NN + bn0 + tx * 4) = r;
    }
}

// ---------------------------------------------------------------------------
// Launch: inputs (metadata order): x, theta, phi_internal, phi_external
// ---------------------------------------------------------------------------
extern "C" void kernel_launch(void* const* d_in, const int* in_sizes, int n_in,
                              void* d_out, int out_size) {
    const float* x       = (const float*)d_in[0];
    const float* theta   = (const float*)d_in[1];
    const float* phi_int = (const float*)d_in[2];
    const float* phi_ext = (const float*)d_in[3];
    float* out = (float*)d_out;

    coef2_kernel<<<TROWS, 128>>>(theta, phi_int);
    build_u_kernel<<<NN / 4, 128>>>(phi_ext);
    gemm_kernel<<<dim3(BATCH / BM, NN / BN), 256>>>(x, out);
}